// round 14
// baseline (speedup 1.0000x reference)
#include <cuda_runtime.h>
#include <cstdint>

#define NBINS 256
#define THREADS 512
#define ELEMS_PER_BATCH (256*32*32)            // 262144
#define I4_PER_BATCH    (ELEMS_PER_BATCH/4)    // 65536
#define I4_PER_THREAD   (I4_PER_BATCH/THREADS) // 128
#define DEPTH 16                               // rolling prefetch distance (regs)
#define GROUPS (I4_PER_THREAD/DEPTH)           // 8
#define GROUP_BYTES (DEPTH*THREADS*16)         // 131072 B per group
#define HIST_WORDS (NBINS*128)                 // 32768 u32 = 128 KB (256 bins x 512 u8 slots)

__device__ __forceinline__ void l2_prefetch_bulk(const void* p, unsigned int bytes) {
    asm volatile("cp.async.bulk.prefetch.L2.global [%0], %1;"
                 :: "l"(p), "r"(bytes) : "memory");
}

__global__ __launch_bounds__(THREADS, 1)
void hist_mode_kernel(const int* __restrict__ in, float* __restrict__ out) {
    extern __shared__ unsigned int hist32[];       // [NBINS][128] u32 view
    unsigned char* hist8 = (unsigned char*)hist32; // [NBINS][512] u8 slots

    const int tid = threadIdx.x;
    const int w = tid >> 5;
    const int l = tid & 31;

    const int4* base = (const int4*)in + (size_t)blockIdx.x * I4_PER_BATCH;

    // Early L2 prefetch of groups 1 and 2 (group 0 is demand-loaded below).
    if (tid == 0) {
        l2_prefetch_bulk((const char*)base + (size_t)1 * GROUP_BYTES, GROUP_BYTES);
        l2_prefetch_bulk((const char*)base + (size_t)2 * GROUP_BYTES, GROUP_BYTES);
    }

    // zero histogram: 8192 uint4 / 512 threads = 16 each
    {
        uint4* z = (uint4*)hist32;
        #pragma unroll
        for (int i = 0; i < HIST_WORDS / 4 / THREADS; i++)
            z[i * THREADS + tid] = make_uint4(0, 0, 0, 0);
    }
    __syncthreads();

    // Byte slot within each bin's 512-byte row:
    //   s = (w>>2)*128 + l*4 + (w&3)
    // word-within-row = (w>>2)*32 + l -> bank = l (conflict-free, bin-independent)
    // warps with the same (w>>2) share words in distinct bytes (byte-enable, no race)
    const int slot = ((w >> 2) << 7) + (l << 2) + (w & 3);
    unsigned char* const sbase = hist8 + slot;

    // Rolling pipeline, depth 16: steady ~16 outstanding loads per thread,
    // hitting L2 thanks to the bulk prefetch running 2 groups ahead.
    int4 buf[DEPTH];
    #pragma unroll
    for (int u = 0; u < DEPTH; u++)
        buf[u] = base[u * THREADS + tid];

    #pragma unroll 1
    for (int g = 0; g < GROUPS - 1; g++) {
        if (tid == 0 && g + 3 < GROUPS)
            l2_prefetch_bulk((const char*)base + (size_t)(g + 3) * GROUP_BYTES,
                             GROUP_BYTES);
        const int4* pre = base + (g + 1) * (DEPTH * THREADS) + tid;
        #pragma unroll
        for (int u = 0; u < DEPTH; u++) {
            const int4 v = buf[u];
            buf[u] = pre[u * THREADS];          // refill slot for g+1 (L2 hit)
            // inputs are guaranteed in [0,256): the value IS the bin
            const unsigned int x0 = (unsigned int)v.x;
            const unsigned int x1 = (unsigned int)v.y;
            const unsigned int x2 = (unsigned int)v.z;
            const unsigned int x3 = (unsigned int)v.w;
            unsigned char* p0 = sbase + (x0 << 9);
            unsigned char* p1 = sbase + (x1 << 9);
            unsigned char* p2 = sbase + (x2 << 9);
            unsigned char* p3 = sbase + (x3 << 9);
            // Pairwise RMW. Same-thread smem ops execute in program order, so
            // the second pair's loads observe the first pair's stores; only the
            // in-flight pair needs a duplicate fix (last store carries the
            // pair's full count).
            const unsigned int a0 = *p0;
            const unsigned int a1 = *p1;
            *p0 = (unsigned char)(a0 + 1u);
            *p1 = (unsigned char)(a1 + 1u + (unsigned)(x0 == x1));
            const unsigned int a2 = *p2;
            const unsigned int a3 = *p3;
            *p2 = (unsigned char)(a2 + 1u);
            *p3 = (unsigned char)(a3 + 1u + (unsigned)(x2 == x3));
        }
    }
    // final group: no refill
    #pragma unroll
    for (int u = 0; u < DEPTH; u++) {
        const int4 v = buf[u];
        const unsigned int x0 = (unsigned int)v.x;
        const unsigned int x1 = (unsigned int)v.y;
        const unsigned int x2 = (unsigned int)v.z;
        const unsigned int x3 = (unsigned int)v.w;
        unsigned char* p0 = sbase + (x0 << 9);
        unsigned char* p1 = sbase + (x1 << 9);
        unsigned char* p2 = sbase + (x2 << 9);
        unsigned char* p3 = sbase + (x3 << 9);
        const unsigned int a0 = *p0;
        const unsigned int a1 = *p1;
        *p0 = (unsigned char)(a0 + 1u);
        *p1 = (unsigned char)(a1 + 1u + (unsigned)(x0 == x1));
        const unsigned int a2 = *p2;
        const unsigned int a3 = *p3;
        *p2 = (unsigned char)(a2 + 1u);
        *p3 = (unsigned char)(a3 + 1u + (unsigned)(x2 == x3));
    }
    __syncthreads();

    // Reduction: thread t sums bin (t&255), half (t>>8) of that bin's 128-word
    // row (64 words), 4 u8 counters per word via dp4a. Rotated -> conflict-free.
    const int fbin  = tid & 255;
    const int fhalf = tid >> 8;
    const unsigned int* frow = hist32 + fbin * 128 + fhalf * 64;
    unsigned int acc = 0;
    #pragma unroll 16
    for (int j = 0; j < 64; j++) {
        const int idx = (j + fbin) & 63;
        acc = __dp4a(frow[idx], 0x01010101u, acc);
    }
    __syncthreads();                 // hist contents consumed; reuse smem
    hist32[tid] = acc;
    __syncthreads();

    if (tid < NBINS) {
        const unsigned int tot = hist32[tid] + hist32[tid + NBINS];
        unsigned int m = tot;
        #pragma unroll
        for (int off = 16; off > 0; off >>= 1)
            m = max(m, __shfl_xor_sync(0xFFFFFFFFu, m, off));
        __syncthreads();
        if (l == 0) hist32[w] = m;
        __syncthreads();
        if (tid == 0) {
            unsigned int mm = hist32[0];
            #pragma unroll
            for (int i = 1; i < NBINS / 32; i++) mm = max(mm, hist32[i]);
            out[blockIdx.x] = (float)mm;
        }
    } else {
        __syncthreads();
        __syncthreads();
    }
}

extern "C" void kernel_launch(void* const* d_in, const int* in_sizes, int n_in,
                              void* d_out, int out_size) {
    const int* in = (const int*)d_in[0];
    float* out = (float*)d_out;
    const int B = out_size; // 128 batch elements, one block each

    const size_t smem = HIST_WORDS * sizeof(unsigned int); // 131072 B
    cudaFuncSetAttribute(hist_mode_kernel,
                         cudaFuncAttributeMaxDynamicSharedMemorySize, (int)smem);
    hist_mode_kernel<<<B, THREADS, smem>>>(in, out);
}

// round 15
// speedup vs baseline: 1.1427x; 1.1427x over previous
#include <cuda_runtime.h>
#include <cstdint>

#define NBINS 256
#define CONS_THREADS 512
#define THREADS 544                            // 16 consumer warps + 1 producer warp
#define ELEMS_PER_BATCH (256*32*32)            // 262144
#define I4_PER_BATCH    (ELEMS_PER_BATCH/4)    // 65536
#define HIST_WORDS (NBINS*128)                 // 32768 u32 = 128 KB
#define RING 3
#define STAGE_BYTES 32768                      // 32 KB per stage
#define STAGE_I4 (STAGE_BYTES/16)              // 2048
#define NSTAGES 32                             // 1 MB / 32 KB
#define I4_PER_THREAD_STAGE 4                  // 2048 int4 / 512 consumer threads

#define HIST_OFF  128
#define STAGE_OFF (HIST_OFF + HIST_WORDS*4)    // 131200 (16B aligned)
#define SMEM_TOTAL (STAGE_OFF + RING*STAGE_BYTES) // 229504 <= 232448

__device__ __forceinline__ uint32_t smem_u32(const void* p) {
    uint32_t a;
    asm("{ .reg .u64 t; cvta.to.shared.u64 t, %1; cvt.u32.u64 %0, t; }"
        : "=r"(a) : "l"(p));
    return a;
}
__device__ __forceinline__ void mbar_init(uint32_t a, uint32_t c) {
    asm volatile("mbarrier.init.shared.b64 [%0], %1;" :: "r"(a), "r"(c) : "memory");
}
__device__ __forceinline__ void mbar_expect_tx(uint32_t a, uint32_t b) {
    asm volatile("mbarrier.arrive.expect_tx.shared.b64 _, [%0], %1;"
                 :: "r"(a), "r"(b) : "memory");
}
__device__ __forceinline__ void mbar_arrive(uint32_t a) {
    asm volatile("mbarrier.arrive.shared.b64 _, [%0];" :: "r"(a) : "memory");
}
__device__ __forceinline__ void mbar_wait(uint32_t a, uint32_t parity) {
    uint32_t done;
    asm volatile(
        "{\n\t.reg .pred p;\n\t"
        "mbarrier.try_wait.parity.acquire.cta.shared::cta.b64 p, [%1], %2;\n\t"
        "selp.b32 %0, 1, 0, p;\n\t}"
        : "=r"(done) : "r"(a), "r"(parity) : "memory");
    if (!done) {
        asm volatile(
            "{\n\t.reg .pred P1;\n\t"
            "WL_%=:\n\t"
            "mbarrier.try_wait.parity.acquire.cta.shared::cta.b64 P1, [%0], %1, 0x989680;\n\t"
            "@P1 bra.uni WD_%=;\n\t"
            "bra.uni WL_%=;\n\t"
            "WD_%=:\n\t}"
            :: "r"(a), "r"(parity) : "memory");
    }
}
__device__ __forceinline__ void bulk_g2s(uint32_t dst, const void* src,
                                         uint32_t bytes, uint32_t mbar) {
    asm volatile(
        "cp.async.bulk.shared::cta.global.mbarrier::complete_tx::bytes "
        "[%0], [%1], %2, [%3];"
        :: "r"(dst), "l"(src), "r"(bytes), "r"(mbar) : "memory");
}

__global__ __launch_bounds__(THREADS, 1)
void hist_mode_kernel(const int* __restrict__ in, float* __restrict__ out) {
    extern __shared__ char smem[];
    unsigned int* hist32 = (unsigned int*)(smem + HIST_OFF);
    unsigned char* hist8 = (unsigned char*)hist32;
    const uint32_t sb = smem_u32(smem);

    const int tid = threadIdx.x;
    const int w = tid >> 5;
    const int l = tid & 31;

    // barriers: full[i] at sb+i*16, empty[i] at sb+i*16+8
    if (tid == 0) {
        #pragma unroll
        for (int i = 0; i < RING; i++) {
            mbar_init(sb + i * 16, 1);       // full: completed by expect_tx + tx bytes
            mbar_init(sb + i * 16 + 8, 16);  // empty: one arrive per consumer warp
        }
    }
    // zero histogram (strided, 544 threads)
    {
        uint4* z = (uint4*)hist32;
        for (int i = tid; i < HIST_WORDS / 4; i += THREADS)
            z[i] = make_uint4(0, 0, 0, 0);
    }
    asm volatile("fence.proxy.async.shared::cta;" ::: "memory");
    __syncthreads();

    const char* gbase = (const char*)((const int4*)in + (size_t)blockIdx.x * I4_PER_BATCH);

    if (w == 16) {
        // ---------------- dedicated producer warp ----------------
        if (l == 0) {
            #pragma unroll
            for (int s = 0; s < RING; s++) {
                mbar_expect_tx(sb + s * 16, STAGE_BYTES);
                bulk_g2s(sb + STAGE_OFF + s * STAGE_BYTES,
                         gbase + (size_t)s * STAGE_BYTES, STAGE_BYTES, sb + s * 16);
            }
        }
        int slot = 0;
        uint32_t parity = 0;
        #pragma unroll 1
        for (int s = RING; s < NSTAGES; s++) {
            mbar_wait(sb + slot * 16 + 8, parity);   // empty (whole warp, uniform)
            if (l == 0) {
                mbar_expect_tx(sb + slot * 16, STAGE_BYTES);
                bulk_g2s(sb + STAGE_OFF + slot * STAGE_BYTES,
                         gbase + (size_t)s * STAGE_BYTES, STAGE_BYTES,
                         sb + slot * 16);
            }
            if (++slot == RING) { slot = 0; parity ^= 1u; }
        }
    } else {
        // ---------------- 16 consumer warps ----------------
        // Byte slot within each bin's 512-byte row: s = (w>>2)*128 + l*4 + (w&3)
        // word-within-row = (w>>2)*32 + l -> bank = l (conflict-free, bin-indep)
        // warps with same (w>>2) share words in distinct bytes (byte-enable, no race)
        const int slotb = ((w >> 2) << 7) + (l << 2) + (w & 3);
        unsigned char* const sbase = hist8 + slotb;

        int slot = 0;
        uint32_t parity = 0;
        #pragma unroll 1
        for (int s = 0; s < NSTAGES; s++) {
            mbar_wait(sb + slot * 16, parity);       // full, acquire

            const int4* sd = (const int4*)(smem + STAGE_OFF + slot * STAGE_BYTES);
            // front-load all staged reads for this stage (independent LDS.128s)
            int4 v[I4_PER_THREAD_STAGE];
            #pragma unroll
            for (int u = 0; u < I4_PER_THREAD_STAGE; u++)
                v[u] = sd[u * CONS_THREADS + tid];

            #pragma unroll
            for (int u = 0; u < I4_PER_THREAD_STAGE; u++) {
                // inputs are guaranteed in [0,256): the value IS the bin
                const unsigned int x0 = (unsigned int)v[u].x;
                const unsigned int x1 = (unsigned int)v[u].y;
                const unsigned int x2 = (unsigned int)v[u].z;
                const unsigned int x3 = (unsigned int)v[u].w;
                unsigned char* p0 = sbase + (x0 << 9);
                unsigned char* p1 = sbase + (x1 << 9);
                unsigned char* p2 = sbase + (x2 << 9);
                unsigned char* p3 = sbase + (x3 << 9);
                // Pairwise RMW; same-thread smem ops are program-ordered, so the
                // second pair's loads observe the first pair's stores; only the
                // in-flight pair needs the duplicate fix.
                const unsigned int a0 = *p0;
                const unsigned int a1 = *p1;
                *p0 = (unsigned char)(a0 + 1u);
                *p1 = (unsigned char)(a1 + 1u + (unsigned)(x0 == x1));
                const unsigned int a2 = *p2;
                const unsigned int a3 = *p3;
                *p2 = (unsigned char)(a2 + 1u);
                *p3 = (unsigned char)(a3 + 1u + (unsigned)(x2 == x3));
            }
            if (l == 0) mbar_arrive(sb + slot * 16 + 8);  // free the stage
            if (++slot == RING) { slot = 0; parity ^= 1u; }
        }
    }
    __syncthreads();

    // Reduction over consumer slots: thread t (t<512) sums bin (t&255),
    // half (t>>8): 64 words, 4 u8 each, via dp4a. Rotated -> conflict-free.
    unsigned int acc = 0;
    if (tid < CONS_THREADS) {
        const int fbin  = tid & 255;
        const int fhalf = tid >> 8;
        const unsigned int* frow = hist32 + fbin * 128 + fhalf * 64;
        #pragma unroll 16
        for (int j = 0; j < 64; j++) {
            const int idx = (j + fbin) & 63;
            acc = __dp4a(frow[idx], 0x01010101u, acc);
        }
    }
    __syncthreads();
    if (tid < CONS_THREADS) hist32[tid] = acc;
    __syncthreads();

    if (tid < NBINS) {
        const unsigned int tot = hist32[tid] + hist32[tid + NBINS];
        unsigned int m = tot;
        #pragma unroll
        for (int off = 16; off > 0; off >>= 1)
            m = max(m, __shfl_xor_sync(0xFFFFFFFFu, m, off));
        __syncthreads();
        if (l == 0) hist32[w] = m;
        __syncthreads();
        if (tid == 0) {
            unsigned int mm = hist32[0];
            #pragma unroll
            for (int i = 1; i < NBINS / 32; i++) mm = max(mm, hist32[i]);
            out[blockIdx.x] = (float)mm;
        }
    } else {
        __syncthreads();
        __syncthreads();
    }
}

extern "C" void kernel_launch(void* const* d_in, const int* in_sizes, int n_in,
                              void* d_out, int out_size) {
    const int* in = (const int*)d_in[0];
    float* out = (float*)d_out;
    const int B = out_size; // 128 batch elements, one block each

    cudaFuncSetAttribute(hist_mode_kernel,
                         cudaFuncAttributeMaxDynamicSharedMemorySize, SMEM_TOTAL);
    hist_mode_kernel<<<B, THREADS, SMEM_TOTAL>>>(in, out);
}